// round 1
// baseline (speedup 1.0000x reference)
#include <cuda_runtime.h>

// Problem constants
#define NV     50000
#define R_DIM  5
#define A_DIM  8
#define C_DIM  64
#define T_DIM  64
#define O_DIM  8
#define RA_DIM 40
#define KSTEPS 41               // 40 gather m-steps + 1 center step
#define KTOT   (KSTEPS * 64)    // 2624
#define NOUT   (O_DIM * T_DIM)  // 512

// GEMM tiling
#define BM 64
#define BN 128
#define BK 64
#define TM 4
#define TN 8

// Folded weights: W'[k][n] with k = m*64+c (m<40) or 2560+c (center),
// n = o*64+t.  2624*512 floats = 5.375 MB (L2-resident).
__device__ float g_W[KTOT * NOUT];

// ---------------------------------------------------------------------------
// Fold the interpolation prior + rotation roll into the neighbor weights:
//   W'[m*64+c][o*64+t] = sum_{r,a} coeff[r,a,m] * nw[t,r,(a+o)%8,c]
// grid = (40 m, 64 t), block = 64 (c). Fully unrolled so the rotated index
// (a+o)&7 is compile-time static (register arrays stay in registers).
// ---------------------------------------------------------------------------
__global__ void fold_neighbor_kernel(const float* __restrict__ nw,
                                     const float* __restrict__ coeff) {
    const int m = blockIdx.x;     // 0..39
    const int t = blockIdx.y;     // 0..63
    const int c = threadIdx.x;    // 0..63

    float nwreg[RA_DIM];
#pragma unroll
    for (int ra = 0; ra < RA_DIM; ra++)
        nwreg[ra] = nw[(t * RA_DIM + ra) * C_DIM + c];   // (T,R,A,C) -> (t, ra, c)

    float coreg[RA_DIM];
#pragma unroll
    for (int ra = 0; ra < RA_DIM; ra++)
        coreg[ra] = coeff[ra * RA_DIM + m];               // (R,A,RA) -> (ra, m)

#pragma unroll
    for (int o = 0; o < O_DIM; o++) {
        float acc = 0.f;
#pragma unroll
        for (int r = 0; r < R_DIM; r++)
#pragma unroll
            for (int a = 0; a < A_DIM; a++)
                acc = fmaf(coreg[r * A_DIM + a],
                           nwreg[r * A_DIM + ((a + o) & 7)], acc);
        g_W[(m * 64 + c) * NOUT + o * T_DIM + t] = acc;
    }
}

// Center fold rows: W'[2560+c][o*64+t] = cw[t,0,c] (replicated over o,
// because conv_center broadcasts across the O dimension).
__global__ void fold_center_kernel(const float* __restrict__ cw) {
    const int t = blockIdx.x;     // 0..63
    const int c = threadIdx.x;    // 0..63
    const float v = cw[t * C_DIM + c];
#pragma unroll
    for (int o = 0; o < O_DIM; o++)
        g_W[(40 * 64 + c) * NOUT + o * T_DIM + t] = v;
}

// ---------------------------------------------------------------------------
// Main fused kernel: per 64-vertex x 128-output tile,
//   A[kk][v] = barycentric-gathered interp0 (or raw mesh row for step 40)
//   B[kk][n] = folded weights (L2-resident)
//   C = relu(A*B + bias[t])
// ---------------------------------------------------------------------------
__global__ __launch_bounds__(256, 2)
void conv_main_kernel(const float* __restrict__ mesh,
                      const float* __restrict__ bary,
                      const float* __restrict__ bias,
                      float* __restrict__ out) {
    __shared__ float As[BK][BM + 4];   // [channel kk][vertex], padded
    __shared__ float Bs[BK][BN];

    const int tid     = threadIdx.x;
    const int vtile   = blockIdx.y * BM;
    const int colBase = blockIdx.x * BN;

    // A-build mapping: 4 threads per vertex, each covers 16 channels
    const int q   = tid & 3;
    const int vl  = tid >> 2;          // 0..63
    const int vg  = vtile + vl;
    const bool vok = (vg < NV);
    const int c0  = q * 16;

    // B-load mapping: warp w loads rows w*8..w*8+7, one float4 per lane
    const int warp = tid >> 5;
    const int lane = tid & 31;

    // Compute mapping: 16x16 thread grid, TM=4 rows x TN=8 cols each
    const int cg = tid & 15;
    const int rg = tid >> 4;

    float acc[TM][TN];
#pragma unroll
    for (int i = 0; i < TM; i++)
#pragma unroll
        for (int j = 0; j < TN; j++) acc[i][j] = 0.f;

    for (int step = 0; step < KSTEPS; step++) {
        // ---- load B tile (L2 hits: g_W is 5.4 MB, shared by all CTAs) ----
#pragma unroll
        for (int rr = 0; rr < 8; rr++) {
            const int kk = warp * 8 + rr;
            const float4 v4 = *reinterpret_cast<const float4*>(
                &g_W[(size_t)(step * 64 + kk) * NOUT + colBase + lane * 4]);
            *reinterpret_cast<float4*>(&Bs[kk][lane * 4]) = v4;
        }

        // ---- build A tile ----
        if (step < 40) {
            int   i0 = 0, i1 = 0, i2 = 0;
            float w0 = 0.f, w1 = 0.f, w2 = 0.f;
            if (vok) {
                // bary layout (N, RA, 3, 2): [i0,w0,i1,w1,i2,w2], 8B-aligned
                const float2* bb = reinterpret_cast<const float2*>(
                    bary + ((size_t)vg * RA_DIM + step) * 6);
                const float2 p0 = bb[0], p1 = bb[1], p2 = bb[2];
                i0 = (int)p0.x; w0 = p0.y;
                i1 = (int)p1.x; w1 = p1.y;
                i2 = (int)p2.x; w2 = p2.y;
            }
            const float* r0 = mesh + (size_t)i0 * C_DIM + c0;
            const float* r1 = mesh + (size_t)i1 * C_DIM + c0;
            const float* r2 = mesh + (size_t)i2 * C_DIM + c0;
#pragma unroll
            for (int j = 0; j < 4; j++) {
                const float4 a0 = *reinterpret_cast<const float4*>(r0 + j * 4);
                const float4 a1 = *reinterpret_cast<const float4*>(r1 + j * 4);
                const float4 a2 = *reinterpret_cast<const float4*>(r2 + j * 4);
                As[c0 + j * 4 + 0][vl] = w0 * a0.x + w1 * a1.x + w2 * a2.x;
                As[c0 + j * 4 + 1][vl] = w0 * a0.y + w1 * a1.y + w2 * a2.y;
                As[c0 + j * 4 + 2][vl] = w0 * a0.z + w1 * a1.z + w2 * a2.z;
                As[c0 + j * 4 + 3][vl] = w0 * a0.w + w1 * a1.w + w2 * a2.w;
            }
        } else {
            // center step: A row is the raw mesh signal
            const float* r0 = mesh + (size_t)(vok ? vg : 0) * C_DIM + c0;
#pragma unroll
            for (int j = 0; j < 4; j++) {
                float4 a0 = *reinterpret_cast<const float4*>(r0 + j * 4);
                if (!vok) a0 = make_float4(0.f, 0.f, 0.f, 0.f);
                As[c0 + j * 4 + 0][vl] = a0.x;
                As[c0 + j * 4 + 1][vl] = a0.y;
                As[c0 + j * 4 + 2][vl] = a0.z;
                As[c0 + j * 4 + 3][vl] = a0.w;
            }
        }
        __syncthreads();

        // ---- FFMA inner loop ----
#pragma unroll
        for (int kk = 0; kk < BK; kk++) {
            float af[TM], bf[TN];
            *reinterpret_cast<float4*>(af) =
                *reinterpret_cast<const float4*>(&As[kk][rg * 4]);
            *reinterpret_cast<float4*>(bf) =
                *reinterpret_cast<const float4*>(&Bs[kk][cg * 8]);
            *reinterpret_cast<float4*>(bf + 4) =
                *reinterpret_cast<const float4*>(&Bs[kk][cg * 8 + 4]);
#pragma unroll
            for (int i = 0; i < TM; i++)
#pragma unroll
                for (int j = 0; j < TN; j++)
                    acc[i][j] = fmaf(af[i], bf[j], acc[i][j]);
        }
        __syncthreads();
    }

    // ---- epilogue: + bias[t], relu, vectorized store ----
    const int col0 = colBase + cg * 8;
    float bv[TN];
#pragma unroll
    for (int j = 0; j < TN; j++) bv[j] = bias[(col0 + j) & 63];

#pragma unroll
    for (int i = 0; i < TM; i++) {
        const int vg2 = vtile + rg * 4 + i;
        if (vg2 < NV) {
            float4 o0, o1;
            o0.x = fmaxf(acc[i][0] + bv[0], 0.f);
            o0.y = fmaxf(acc[i][1] + bv[1], 0.f);
            o0.z = fmaxf(acc[i][2] + bv[2], 0.f);
            o0.w = fmaxf(acc[i][3] + bv[3], 0.f);
            o1.x = fmaxf(acc[i][4] + bv[4], 0.f);
            o1.y = fmaxf(acc[i][5] + bv[5], 0.f);
            o1.z = fmaxf(acc[i][6] + bv[6], 0.f);
            o1.w = fmaxf(acc[i][7] + bv[7], 0.f);
            *reinterpret_cast<float4*>(&out[(size_t)vg2 * NOUT + col0])     = o0;
            *reinterpret_cast<float4*>(&out[(size_t)vg2 * NOUT + col0 + 4]) = o1;
        }
    }
}

extern "C" void kernel_launch(void* const* d_in, const int* in_sizes, int n_in,
                              void* d_out, int out_size) {
    const float* mesh  = (const float*)d_in[0];  // (50000, 64)
    const float* bary  = (const float*)d_in[1];  // (50000, 5, 8, 3, 2)
    const float* nw    = (const float*)d_in[2];  // (64, 5, 8, 64)
    const float* cw    = (const float*)d_in[3];  // (64, 1, 64)
    const float* bias  = (const float*)d_in[4];  // (64,)
    const float* coeff = (const float*)d_in[5];  // (5, 8, 40)
    float* out = (float*)d_out;                  // (50000, 8, 64)

    fold_neighbor_kernel<<<dim3(40, 64), 64>>>(nw, coeff);
    fold_center_kernel<<<64, 64>>>(cw);

    const int vtiles = (NV + BM - 1) / BM;       // 782
    conv_main_kernel<<<dim3(NOUT / BN, vtiles), 256>>>(mesh, bary, bias, out);
}

// round 3
// speedup vs baseline: 2.5258x; 2.5258x over previous
#include <cuda_runtime.h>
#include <cstdint>

#define NV      50000
#define BM      128
#define NVT     ((NV + BM - 1) / BM)   // 391
#define CHUNKS  41
#define A_STRIDE 68                    // floats per vertex row (pad vs 64)

// SMEM byte offsets
#define SM_A0    0
#define SM_A1    34816                 // 128*68*4
#define SM_B0    69632
#define SM_B1    135168                // +64KB
#define SM_BIAS  200704
#define SMEM_TOTAL 200960

// Folded weights, tf32 bit patterns, fragment-major, chunk-blocked:
// [nt(2)][chunk(41)][wn(4)][t(8)][ks(8)][lane(32)][reg(2)] -> 5.375 MB
__device__ __align__(256) unsigned g_W[2u * 41 * 65536 / 4];

// ---------------------------------------------------------------------------
// helpers (all baseline PTX: sm_80+)
// ---------------------------------------------------------------------------
__device__ __forceinline__ unsigned f2tf32(float x) {
    unsigned u;
    asm("cvt.rna.tf32.f32 %0, %1;" : "=r"(u) : "f"(x));
    return u;
}
__device__ __forceinline__ uint32_t smem_u32(const void* p) {
    uint32_t a;
    asm("{ .reg .u64 t; cvta.to.shared.u64 t, %1; cvt.u32.u64 %0, t; }"
        : "=r"(a) : "l"(p));
    return a;
}
__device__ __forceinline__ void cp16(uint32_t d, const void* s) {
    asm volatile("cp.async.cg.shared.global [%0], [%1], 16;"
                 :: "r"(d), "l"(s) : "memory");
}
__device__ __forceinline__ void cp_commit() {
    asm volatile("cp.async.commit_group;" ::: "memory");
}
__device__ __forceinline__ void cp_wait0() {
    asm volatile("cp.async.wait_group 0;" ::: "memory");
}
__device__ __forceinline__ void mma8(float* d, const unsigned* a, const unsigned* b) {
    asm volatile(
        "mma.sync.aligned.m16n8k8.row.col.f32.tf32.tf32.f32 "
        "{%0,%1,%2,%3}, {%4,%5,%6,%7}, {%8,%9}, {%0,%1,%2,%3};"
        : "+f"(d[0]), "+f"(d[1]), "+f"(d[2]), "+f"(d[3])
        : "r"(a[0]), "r"(a[1]), "r"(a[2]), "r"(a[3]), "r"(b[0]), "r"(b[1]));
}

// ---------------------------------------------------------------------------
// Fold kernel: W'[k=(m,c)][n=(o,t)] = sum_{r2,a2} coeff[r2,a2,m] * nw[t,r2,(a2+o)&7,c]
// (m=40 -> center row = cw[t][c], replicated over o). Written tf32,
// fragment-major per the g_W layout above.
// ---------------------------------------------------------------------------
__global__ void fold_kernel(const float* __restrict__ nw,
                            const float* __restrict__ cw,
                            const float* __restrict__ coeff) {
    const int m = blockIdx.x;    // 0..40
    const int t = blockIdx.y;    // 0..63
    const int c = threadIdx.x;   // 0..63

    float vals[8];
    if (m < 40) {
        float nwreg[40], coreg[40];
#pragma unroll
        for (int ra = 0; ra < 40; ra++)
            nwreg[ra] = nw[(t * 40 + ra) * 64 + c];
#pragma unroll
        for (int ra = 0; ra < 40; ra++)
            coreg[ra] = coeff[ra * 40 + m];
#pragma unroll
        for (int o = 0; o < 8; o++) {
            float acc = 0.f;
#pragma unroll
            for (int r = 0; r < 5; r++)
#pragma unroll
                for (int a = 0; a < 8; a++)
                    acc = fmaf(coreg[r * 8 + a], nwreg[r * 8 + ((a + o) & 7)], acc);
            vals[o] = acc;
        }
    } else {
        const float vv = cw[t * 64 + c];
#pragma unroll
        for (int o = 0; o < 8; o++) vals[o] = vv;
    }

    const int ks = c >> 3, kk = c & 7, reg = kk >> 2;
#pragma unroll
    for (int o = 0; o < 8; o++) {
        const int n  = o * 64 + t;
        const int nt = n >> 8, w = (n >> 6) & 3, tt = (n >> 3) & 7;
        const int lane = (n & 7) * 4 + (kk & 3);
        const size_t idx =
            ((((size_t)(nt * 41 + m) * 4 + w) * 8 + tt) * 8 + ks) * 64 + lane * 2 + reg;
        g_W[idx] = f2tf32(vals[o]);
    }
}

// ---------------------------------------------------------------------------
// A-tile builder: barycentric gather + interp + tf32 cvt into As[v][c] (pad 68).
// 2 threads per vertex, each handles 32 contiguous channels.
// ---------------------------------------------------------------------------
__device__ __forceinline__ void build_a(float* Adst, const float* __restrict__ mesh,
                                        int chunk, int v, int h, int vcl,
                                        float2 p0, float2 p1, float2 p2) {
    float w0, w1, w2;
    const float4 *r0, *r1, *r2;
    if (chunk < 40) {
        w0 = p0.y; w1 = p1.y; w2 = p2.y;
        r0 = (const float4*)(mesh + (size_t)(int)p0.x * 64 + h * 32);
        r1 = (const float4*)(mesh + (size_t)(int)p1.x * 64 + h * 32);
        r2 = (const float4*)(mesh + (size_t)(int)p2.x * 64 + h * 32);
    } else {  // center: raw mesh row
        w0 = 1.f; w1 = 0.f; w2 = 0.f;
        r0 = r1 = r2 = (const float4*)(mesh + (size_t)vcl * 64 + h * 32);
    }
    unsigned* dst = (unsigned*)(Adst + v * A_STRIDE + h * 32);
#pragma unroll
    for (int j = 0; j < 8; j++) {
        const float4 a0 = r0[j], a1 = r1[j], a2 = r2[j];
        uint4 u;
        u.x = f2tf32(fmaf(w0, a0.x, fmaf(w1, a1.x, w2 * a2.x)));
        u.y = f2tf32(fmaf(w0, a0.y, fmaf(w1, a1.y, w2 * a2.y)));
        u.z = f2tf32(fmaf(w0, a0.z, fmaf(w1, a1.z, w2 * a2.z)));
        u.w = f2tf32(fmaf(w0, a0.w, fmaf(w1, a1.w, w2 * a2.w)));
        *(uint4*)(dst + j * 4) = u;
    }
}

// ---------------------------------------------------------------------------
// Main kernel: 256 threads, 8 warps (2 M-rows x 4 N-cols), warp tile 64x64.
// Double-buffered A (gather) + B (cp.async from g_W), mma.sync tf32 inner loop.
// ---------------------------------------------------------------------------
__global__ __launch_bounds__(256, 1)
void conv_mma_kernel(const float* __restrict__ mesh,
                     const float* __restrict__ bary,
                     const float* __restrict__ bias,
                     float* __restrict__ out) {
    extern __shared__ __align__(128) char smem[];
    const uint32_t sbase = smem_u32(smem);

    const int tid  = threadIdx.x;
    const int lane = tid & 31;
    const int wid  = tid >> 5;
    const int wm   = wid >> 2;           // 0..1
    const int wn   = wid & 3;            // 0..3
    const int nt   = blockIdx.x;         // 0..1
    const int vt   = blockIdx.y;         // 0..390

    if (tid < 64) ((float*)(smem + SM_BIAS))[tid] = bias[tid];

    const char* gW = (const char*)g_W + (size_t)nt * 41 * 65536;
    const int v   = tid >> 1;            // 0..127 (local vertex)
    const int h   = tid & 1;             // channel half
    const int vg  = vt * BM + v;
    const int vcl = vg < NV ? vg : NV - 1;
    const float* bary_v = bary + (size_t)vcl * 240;   // 40*3*2

    float acc[4][8][4];
#pragma unroll
    for (int mt = 0; mt < 4; mt++)
#pragma unroll
        for (int t = 0; t < 8; t++)
#pragma unroll
            for (int q = 0; q < 4; q++) acc[mt][t][q] = 0.f;

    // ---------------- prologue: stage 0 ----------------
    {
        const uint32_t bdst = sbase + SM_B0 + tid * 16;
        const char*    bsrc = gW + tid * 16;
#pragma unroll
        for (int i = 0; i < 16; i++) cp16(bdst + i * 4096, bsrc + i * 4096);
        cp_commit();
        const float2 p0 = *(const float2*)(bary_v + 0);
        const float2 p1 = *(const float2*)(bary_v + 2);
        const float2 p2 = *(const float2*)(bary_v + 4);
        build_a((float*)(smem + SM_A0), mesh, 0, v, h, vcl, p0, p1, p2);
        cp_wait0();
        __syncthreads();
    }

    // ---------------- main loop ----------------
    for (int c = 0; c < CHUNKS; c++) {
        const int s   = c & 1;
        const int ncn = c + 1;
        float2 p0 = make_float2(0.f, 0.f), p1 = p0, p2 = p0;

        if (ncn < CHUNKS) {
            // issue B load for next chunk into buffer s^1
            const uint32_t bdst = sbase + (s ? SM_B0 : SM_B1) + tid * 16;
            const char*    bsrc = gW + (size_t)ncn * 65536 + tid * 16;
#pragma unroll
            for (int i = 0; i < 16; i++) cp16(bdst + i * 4096, bsrc + i * 4096);
            cp_commit();
            if (ncn < 40) {   // prefetch bary (DRAM latency hidden by mma)
                p0 = *(const float2*)(bary_v + ncn * 6 + 0);
                p1 = *(const float2*)(bary_v + ncn * 6 + 2);
                p2 = *(const float2*)(bary_v + ncn * 6 + 4);
            }
        }

        // ---- mma over buffers s ----
        const unsigned* Ab = (const unsigned*)(smem + (s ? SM_A1 : SM_A0));
        const float*    Bb = (const float*)(smem + (s ? SM_B1 : SM_B0));
#pragma unroll
        for (int ks = 0; ks < 8; ks++) {
            unsigned af[4][4];
#pragma unroll
            for (int mt = 0; mt < 4; mt++) {
                const unsigned* ap = Ab +
                    (wm * 64 + mt * 16 + (lane >> 2)) * A_STRIDE + ks * 8 + (lane & 3);
                af[mt][0] = ap[0];
                af[mt][1] = ap[8 * A_STRIDE];
                af[mt][2] = ap[4];
                af[mt][3] = ap[8 * A_STRIDE + 4];
            }
            unsigned bf[8][2];
#pragma unroll
            for (int t = 0; t < 8; t++) {
                const float2 bv = *(const float2*)(Bb + (((wn * 8 + t) * 8 + ks) * 64) + lane * 2);
                bf[t][0] = __float_as_uint(bv.x);
                bf[t][1] = __float_as_uint(bv.y);
            }
#pragma unroll
            for (int mt = 0; mt < 4; mt++)
#pragma unroll
                for (int t = 0; t < 8; t++)
                    mma8(acc[mt][t], af[mt], bf[t]);
        }

        // ---- build next A into buffer s^1 ----
        if (ncn < CHUNKS)
            build_a((float*)(smem + (s ? SM_A0 : SM_A1)), mesh, ncn, v, h, vcl,
                    p0, p1, p2);

        cp_wait0();
        __syncthreads();
    }

    // ---------------- epilogue: +bias, relu, store ----------------
    const float* sbias = (const float*)(smem + SM_BIAS);
#pragma unroll
    for (int mt = 0; mt < 4; mt++) {
        const int row0 = vt * BM + wm * 64 + mt * 16 + (lane >> 2);
        const int row1 = row0 + 8;
#pragma unroll
        for (int t = 0; t < 8; t++) {
            const int cloc = t * 8 + (lane & 3) * 2;           // 0..63
            const int col  = nt * 256 + wn * 64 + cloc;
            const float b0 = sbias[cloc & 63];
            const float b1 = sbias[(cloc + 1) & 63];
            if (row0 < NV) {
                float2 o0;
                o0.x = fmaxf(acc[mt][t][0] + b0, 0.f);
                o0.y = fmaxf(acc[mt][t][1] + b1, 0.f);
                *(float2*)(out + (size_t)row0 * 512 + col) = o0;
            }
            if (row1 < NV) {
                float2 o1;
                o1.x = fmaxf(acc[mt][t][2] + b0, 0.f);
                o1.y = fmaxf(acc[mt][t][3] + b1, 0.f);
                *(float2*)(out + (size_t)row1 * 512 + col) = o1;
            }
        }
    }
}

extern "C" void kernel_launch(void* const* d_in, const int* in_sizes, int n_in,
                              void* d_out, int out_size) {
    const float* mesh  = (const float*)d_in[0];  // (50000, 64)
    const float* bary  = (const float*)d_in[1];  // (50000, 5, 8, 3, 2)
    const float* nw    = (const float*)d_in[2];  // (64, 5, 8, 64)
    const float* cw    = (const float*)d_in[3];  // (64, 1, 64)
    const float* bias  = (const float*)d_in[4];  // (64,)
    const float* coeff = (const float*)d_in[5];  // (5, 8, 40)
    float* out = (float*)d_out;                  // (50000, 8, 64)

    static int smem_set = 0;
    if (!smem_set) {
        cudaFuncSetAttribute(conv_mma_kernel,
                             cudaFuncAttributeMaxDynamicSharedMemorySize, SMEM_TOTAL);
        smem_set = 1;
    }

    fold_kernel<<<dim3(41, 64), 64>>>(nw, cw, coeff);
    conv_mma_kernel<<<dim3(2, NVT), 256, SMEM_TOTAL>>>(mesh, bary, bias, out);
}

// round 5
// speedup vs baseline: 4.1432x; 1.6403x over previous
#include <cuda_runtime.h>
#include <cstdint>

#define NV      50000
#define BM      128
#define NVT     ((NV + BM - 1) / BM)   // 391
#define CHUNKS  41
#define A_STRIDE 68                    // floats per vertex row (pad vs 64)

// SMEM byte offsets
#define SM_A0    0
#define SM_A1    34816                 // 128*68*4
#define SM_B0    69632
#define SM_B1    135168                // +64KB
#define SM_BIAS  200704
#define SMEM_TOTAL 200960

// Folded weights, tf32 bit patterns, fragment-major, chunk-blocked:
// [nt(2)][chunk(41)][w(4)][tt(8)][ks(8)][lane(32)][reg(2)] -> 5.375 MB
__device__ __align__(256) unsigned g_W[2u * 41 * 65536 / 4];

// ---------------------------------------------------------------------------
// helpers (all baseline PTX: sm_80+)
// ---------------------------------------------------------------------------
__device__ __forceinline__ unsigned f2tf32(float x) {
    unsigned u;
    asm("cvt.rna.tf32.f32 %0, %1;" : "=r"(u) : "f"(x));
    return u;
}
__device__ __forceinline__ uint32_t smem_u32(const void* p) {
    uint32_t a;
    asm("{ .reg .u64 t; cvta.to.shared.u64 t, %1; cvt.u32.u64 %0, t; }"
        : "=r"(a) : "l"(p));
    return a;
}
__device__ __forceinline__ void cp16(uint32_t d, const void* s) {
    asm volatile("cp.async.cg.shared.global [%0], [%1], 16;"
                 :: "r"(d), "l"(s) : "memory");
}
__device__ __forceinline__ void cp_commit() {
    asm volatile("cp.async.commit_group;" ::: "memory");
}
__device__ __forceinline__ void cp_wait0() {
    asm volatile("cp.async.wait_group 0;" ::: "memory");
}
__device__ __forceinline__ void mma8(float* d, const unsigned* a, const unsigned* b) {
    asm volatile(
        "mma.sync.aligned.m16n8k8.row.col.f32.tf32.tf32.f32 "
        "{%0,%1,%2,%3}, {%4,%5,%6,%7}, {%8,%9}, {%0,%1,%2,%3};"
        : "+f"(d[0]), "+f"(d[1]), "+f"(d[2]), "+f"(d[3])
        : "r"(a[0]), "r"(a[1]), "r"(a[2]), "r"(a[3]), "r"(b[0]), "r"(b[1]));
}

// ---------------------------------------------------------------------------
// Fold kernel: W'[k=(m,c)][n=(o,t)] = sum_{r2,a2} coeff[r2,a2,m] * nw[t,r2,(a2+o)&7,c]
// (m=40 -> center row = cw[t][c], replicated over o). Written tf32,
// fragment-major per the g_W layout above.
// ---------------------------------------------------------------------------
__global__ void fold_kernel(const float* __restrict__ nw,
                            const float* __restrict__ cw,
                            const float* __restrict__ coeff) {
    const int m = blockIdx.x;    // 0..40
    const int t = blockIdx.y;    // 0..63
    const int c = threadIdx.x;   // 0..63

    float vals[8];
    if (m < 40) {
        float nwreg[40], coreg[40];
#pragma unroll
        for (int ra = 0; ra < 40; ra++)
            nwreg[ra] = nw[(t * 40 + ra) * 64 + c];
#pragma unroll
        for (int ra = 0; ra < 40; ra++)
            coreg[ra] = coeff[ra * 40 + m];
#pragma unroll
        for (int o = 0; o < 8; o++) {
            float acc = 0.f;
#pragma unroll
            for (int r = 0; r < 5; r++)
#pragma unroll
                for (int a = 0; a < 8; a++)
                    acc = fmaf(coreg[r * 8 + a], nwreg[r * 8 + ((a + o) & 7)], acc);
            vals[o] = acc;
        }
    } else {
        const float vv = cw[t * 64 + c];
#pragma unroll
        for (int o = 0; o < 8; o++) vals[o] = vv;
    }

    const int ks = c >> 3, kk = c & 7, reg = kk >> 2;
#pragma unroll
    for (int o = 0; o < 8; o++) {
        const int n  = o * 64 + t;
        const int nt = n >> 8, w = (n >> 6) & 3, tt = (n >> 3) & 7;
        const int lane = (n & 7) * 4 + (kk & 3);
        const size_t idx =
            ((((size_t)(nt * 41 + m) * 4 + w) * 8 + tt) * 8 + ks) * 64 + lane * 2 + reg;
        g_W[idx] = f2tf32(vals[o]);
    }
}

// ---------------------------------------------------------------------------
// A-tile builder: barycentric gather + interp + tf32 cvt into As[v][c] (pad 68).
// 4 threads per vertex, each handles 16 contiguous channels.
// ---------------------------------------------------------------------------
__device__ __forceinline__ void build_a(float* Adst, const float* __restrict__ mesh,
                                        int chunk, int v, int c0, int vcl,
                                        float2 p0, float2 p1, float2 p2) {
    float w0, w1, w2;
    const float4 *r0, *r1, *r2;
    if (chunk < 40) {
        w0 = p0.y; w1 = p1.y; w2 = p2.y;
        r0 = (const float4*)(mesh + (size_t)(int)p0.x * 64 + c0);
        r1 = (const float4*)(mesh + (size_t)(int)p1.x * 64 + c0);
        r2 = (const float4*)(mesh + (size_t)(int)p2.x * 64 + c0);
    } else {  // center: raw mesh row
        w0 = 1.f; w1 = 0.f; w2 = 0.f;
        r0 = r1 = r2 = (const float4*)(mesh + (size_t)vcl * 64 + c0);
    }
    unsigned* dst = (unsigned*)(Adst + v * A_STRIDE + c0);
#pragma unroll
    for (int j = 0; j < 4; j++) {
        const float4 a0 = r0[j], a1 = r1[j], a2 = r2[j];
        uint4 u;
        u.x = f2tf32(fmaf(w0, a0.x, fmaf(w1, a1.x, w2 * a2.x)));
        u.y = f2tf32(fmaf(w0, a0.y, fmaf(w1, a1.y, w2 * a2.y)));
        u.z = f2tf32(fmaf(w0, a0.z, fmaf(w1, a1.z, w2 * a2.z)));
        u.w = f2tf32(fmaf(w0, a0.w, fmaf(w1, a1.w, w2 * a2.w)));
        *(uint4*)(dst + j * 4) = u;
    }
}

// ---------------------------------------------------------------------------
// Main kernel: 512 threads, 16 warps (2 M-rows x 8 N-cols), warp tile 64x32.
// Double-buffered A (gather) + B (cp.async from g_W), mma.sync tf32 inner loop.
// ---------------------------------------------------------------------------
__global__ __launch_bounds__(512, 1)
void conv_mma_kernel(const float* __restrict__ mesh,
                     const float* __restrict__ bary,
                     const float* __restrict__ bias,
                     float* __restrict__ out) {
    extern __shared__ __align__(128) char smem[];
    const uint32_t sbase = smem_u32(smem);

    const int tid  = threadIdx.x;
    const int lane = tid & 31;
    const int wid  = tid >> 5;
    const int wm   = wid >> 3;           // 0..1
    const int wn2  = wid & 7;            // 0..7  (32-col groups)
    const int w4   = wn2 >> 1;           // 64-col group index (matches g_W 'w')
    const int thal = (wn2 & 1) * 4;      // tt offset within the 64-col group
    const int nt   = blockIdx.x;         // 0..1
    const int vt   = blockIdx.y;         // 0..390

    if (tid < 64) ((float*)(smem + SM_BIAS))[tid] = bias[tid];

    const char* gW = (const char*)g_W + (size_t)nt * 41 * 65536;
    const int v   = tid >> 2;            // 0..127 (local vertex)
    const int c0  = (tid & 3) * 16;      // channel quarter
    const int vg  = vt * BM + v;
    const int vcl = vg < NV ? vg : NV - 1;
    const float* bary_v = bary + (size_t)vcl * 240;   // 40*3*2

    float acc[4][4][4];
#pragma unroll
    for (int mt = 0; mt < 4; mt++)
#pragma unroll
        for (int t = 0; t < 4; t++)
#pragma unroll
            for (int q = 0; q < 4; q++) acc[mt][t][q] = 0.f;

    // ---------------- prologue: stage 0 ----------------
    {
        const uint32_t bdst = sbase + SM_B0 + tid * 16;
        const char*    bsrc = gW + tid * 16;
#pragma unroll
        for (int i = 0; i < 8; i++) cp16(bdst + i * 8192, bsrc + i * 8192);
        cp_commit();
        const float2 p0 = *(const float2*)(bary_v + 0);
        const float2 p1 = *(const float2*)(bary_v + 2);
        const float2 p2 = *(const float2*)(bary_v + 4);
        build_a((float*)(smem + SM_A0), mesh, 0, v, c0, vcl, p0, p1, p2);
        cp_wait0();
        __syncthreads();
    }

    // ---------------- main loop ----------------
    for (int c = 0; c < CHUNKS; c++) {
        const int s   = c & 1;
        const int ncn = c + 1;
        float2 p0 = make_float2(0.f, 0.f), p1 = p0, p2 = p0;

        if (ncn < CHUNKS) {
            // issue B load for next chunk into buffer s^1
            const uint32_t bdst = sbase + (s ? SM_B0 : SM_B1) + tid * 16;
            const char*    bsrc = gW + (size_t)ncn * 65536 + tid * 16;
#pragma unroll
            for (int i = 0; i < 8; i++) cp16(bdst + i * 8192, bsrc + i * 8192);
            cp_commit();
            if (ncn < 40) {   // prefetch bary (DRAM latency hidden by mma)
                p0 = *(const float2*)(bary_v + ncn * 6 + 0);
                p1 = *(const float2*)(bary_v + ncn * 6 + 2);
                p2 = *(const float2*)(bary_v + ncn * 6 + 4);
            }
        }

        // ---- mma over buffers s ----
        const unsigned* Ab = (const unsigned*)(smem + (s ? SM_A1 : SM_A0));
        const float*    Bb = (const float*)(smem + (s ? SM_B1 : SM_B0));
#pragma unroll
        for (int ks = 0; ks < 8; ks++) {
            unsigned af[4][4];
#pragma unroll
            for (int mt = 0; mt < 4; mt++) {
                const unsigned* ap = Ab +
                    (wm * 64 + mt * 16 + (lane >> 2)) * A_STRIDE + ks * 8 + (lane & 3);
                af[mt][0] = ap[0];
                af[mt][1] = ap[8 * A_STRIDE];
                af[mt][2] = ap[4];
                af[mt][3] = ap[8 * A_STRIDE + 4];
            }
            unsigned bf[4][2];
#pragma unroll
            for (int t = 0; t < 4; t++) {
                const float2 bv = *(const float2*)(Bb +
                    (((w4 * 8 + thal + t) * 8 + ks) * 64) + lane * 2);
                bf[t][0] = __float_as_uint(bv.x);
                bf[t][1] = __float_as_uint(bv.y);
            }
#pragma unroll
            for (int mt = 0; mt < 4; mt++)
#pragma unroll
                for (int t = 0; t < 4; t++)
                    mma8(acc[mt][t], af[mt], bf[t]);
        }

        // ---- build next A into buffer s^1 ----
        if (ncn < CHUNKS)
            build_a((float*)(smem + (s ? SM_A0 : SM_A1)), mesh, ncn, v, c0, vcl,
                    p0, p1, p2);

        cp_wait0();
        __syncthreads();
    }

    // ---------------- epilogue: +bias, relu, store ----------------
    const float* sbias = (const float*)(smem + SM_BIAS);
#pragma unroll
    for (int mt = 0; mt < 4; mt++) {
        const int row0 = vt * BM + wm * 64 + mt * 16 + (lane >> 2);
        const int row1 = row0 + 8;
#pragma unroll
        for (int t = 0; t < 4; t++) {
            const int cloc = (thal + t) * 8 + (lane & 3) * 2;  // 0..63 within group
            const int col  = nt * 256 + w4 * 64 + cloc;
            const float b0 = sbias[cloc];
            const float b1 = sbias[cloc + 1];
            if (row0 < NV) {
                float2 o0;
                o0.x = fmaxf(acc[mt][t][0] + b0, 0.f);
                o0.y = fmaxf(acc[mt][t][1] + b1, 0.f);
                *(float2*)(out + (size_t)row0 * 512 + col) = o0;
            }
            if (row1 < NV) {
                float2 o1;
                o1.x = fmaxf(acc[mt][t][2] + b0, 0.f);
                o1.y = fmaxf(acc[mt][t][3] + b1, 0.f);
                *(float2*)(out + (size_t)row1 * 512 + col) = o1;
            }
        }
    }
}

extern "C" void kernel_launch(void* const* d_in, const int* in_sizes, int n_in,
                              void* d_out, int out_size) {
    const float* mesh  = (const float*)d_in[0];  // (50000, 64)
    const float* bary  = (const float*)d_in[1];  // (50000, 5, 8, 3, 2)
    const float* nw    = (const float*)d_in[2];  // (64, 5, 8, 64)
    const float* cw    = (const float*)d_in[3];  // (64, 1, 64)
    const float* bias  = (const float*)d_in[4];  // (64,)
    const float* coeff = (const float*)d_in[5];  // (5, 8, 40)
    float* out = (float*)d_out;                  // (50000, 8, 64)

    static int smem_set = 0;
    if (!smem_set) {
        cudaFuncSetAttribute(conv_mma_kernel,
                             cudaFuncAttributeMaxDynamicSharedMemorySize, SMEM_TOTAL);
        smem_set = 1;
    }

    fold_kernel<<<dim3(41, 64), 64>>>(nw, cw, coeff);
    conv_mma_kernel<<<dim3(2, NVT), 512, SMEM_TOTAL>>>(mesh, bary, bias, out);
}

// round 9
// speedup vs baseline: 4.5839x; 1.1064x over previous
#include <cuda_runtime.h>
#include <cstdint>

#define NV      50000
#define BM      128
#define NVT     ((NV + BM - 1) / BM)   // 391
#define CHUNKS  41
#define A_STRIDE 68                    // floats per vertex row (pad vs 64)

// SMEM byte offsets
#define SM_A0    0
#define SM_A1    34816                 // 128*68*4
#define SM_B0    69632
#define SM_B1    135168                // +64KB
#define SM_BIAS  200704
#define SMEM_TOTAL 200960

// Folded weights, tf32 bit patterns, fragment-major, chunk-blocked, B-paired:
// [nt(2)][chunk(41)][w(4)][pair(4)][ks(8)][lane(32)][inpair(2)][reg(2)] -> 5.375MB
__device__ __align__(256) unsigned g_W[2u * 41 * 65536 / 4];

// ---------------------------------------------------------------------------
// helpers (all baseline PTX: sm_80+; ldmatrix is sm_75+)
// ---------------------------------------------------------------------------
__device__ __forceinline__ unsigned f2tf32(float x) {
    unsigned u;
    asm("cvt.rna.tf32.f32 %0, %1;" : "=r"(u) : "f"(x));
    return u;
}
__device__ __forceinline__ uint32_t smem_u32(const void* p) {
    uint32_t a;
    asm("{ .reg .u64 t; cvta.to.shared.u64 t, %1; cvt.u32.u64 %0, t; }"
        : "=r"(a) : "l"(p));
    return a;
}
__device__ __forceinline__ void cp16(uint32_t d, const void* s) {
    asm volatile("cp.async.cg.shared.global [%0], [%1], 16;"
                 :: "r"(d), "l"(s) : "memory");
}
__device__ __forceinline__ void cp_commit() {
    asm volatile("cp.async.commit_group;" ::: "memory");
}
__device__ __forceinline__ void cp_wait0() {
    asm volatile("cp.async.wait_group 0;" ::: "memory");
}
__device__ __forceinline__ void ldmA(unsigned* r, uint32_t addr) {
    asm volatile("ldmatrix.sync.aligned.m8n8.x4.shared.b16 {%0,%1,%2,%3}, [%4];"
                 : "=r"(r[0]), "=r"(r[1]), "=r"(r[2]), "=r"(r[3]) : "r"(addr));
}
__device__ __forceinline__ void mma8(float* d, const unsigned* a, const unsigned* b) {
    asm volatile(
        "mma.sync.aligned.m16n8k8.row.col.f32.tf32.tf32.f32 "
        "{%0,%1,%2,%3}, {%4,%5,%6,%7}, {%8,%9}, {%0,%1,%2,%3};"
        : "+f"(d[0]), "+f"(d[1]), "+f"(d[2]), "+f"(d[3])
        : "r"(a[0]), "r"(a[1]), "r"(a[2]), "r"(a[3]), "r"(b[0]), "r"(b[1]));
}

// ---------------------------------------------------------------------------
// Fold kernel: W'[k=(m,c)][n=(o,t)] = sum_{r2,a2} coeff[r2,a2,m] * nw[t,r2,(a2+o)&7,c]
// (m=40 -> center row = cw[t][c], replicated over o). Written tf32,
// fragment-major (B-fragments paired for LDS.128) per the g_W layout above.
// ---------------------------------------------------------------------------
__global__ void fold_kernel(const float* __restrict__ nw,
                            const float* __restrict__ cw,
                            const float* __restrict__ coeff) {
    const int m = blockIdx.x;    // 0..40
    const int t = blockIdx.y;    // 0..63
    const int c = threadIdx.x;   // 0..63

    float vals[8];
    if (m < 40) {
        float nwreg[40], coreg[40];
#pragma unroll
        for (int ra = 0; ra < 40; ra++)
            nwreg[ra] = nw[(t * 40 + ra) * 64 + c];
#pragma unroll
        for (int ra = 0; ra < 40; ra++)
            coreg[ra] = coeff[ra * 40 + m];
#pragma unroll
        for (int o = 0; o < 8; o++) {
            float acc = 0.f;
#pragma unroll
            for (int r = 0; r < 5; r++)
#pragma unroll
                for (int a = 0; a < 8; a++)
                    acc = fmaf(coreg[r * 8 + a], nwreg[r * 8 + ((a + o) & 7)], acc);
            vals[o] = acc;
        }
    } else {
        const float vv = cw[t * 64 + c];
#pragma unroll
        for (int o = 0; o < 8; o++) vals[o] = vv;
    }

    const int ks = c >> 3, kk = c & 7, reg = kk >> 2;
#pragma unroll
    for (int o = 0; o < 8; o++) {
        const int n    = o * 64 + t;
        const int nt   = n >> 8, w = (n >> 6) & 3, tt = (n >> 3) & 7;
        const int pair = tt >> 1, inp = tt & 1;
        const int lane = (n & 7) * 4 + (kk & 3);
        const size_t idx =
            ((((((size_t)(nt * 41 + m) * 4 + w) * 4 + pair) * 8 + ks) * 32 + lane) * 2
             + inp) * 2 + reg;
        g_W[idx] = f2tf32(vals[o]);
    }
}

// ---------------------------------------------------------------------------
// A-tile builder: barycentric gather + interp + tf32 cvt into As[v][c] (pad 68).
// 4 threads per vertex, each handles 16 contiguous channels.
// ---------------------------------------------------------------------------
__device__ __forceinline__ void build_a(float* Adst, const float* __restrict__ mesh,
                                        int chunk, int v, int c0, int vcl,
                                        float2 p0, float2 p1, float2 p2) {
    float w0, w1, w2;
    const float4 *r0, *r1, *r2;
    if (chunk < 40) {
        w0 = p0.y; w1 = p1.y; w2 = p2.y;
        r0 = (const float4*)(mesh + (size_t)(int)p0.x * 64 + c0);
        r1 = (const float4*)(mesh + (size_t)(int)p1.x * 64 + c0);
        r2 = (const float4*)(mesh + (size_t)(int)p2.x * 64 + c0);
    } else {  // center: raw mesh row
        w0 = 1.f; w1 = 0.f; w2 = 0.f;
        r0 = r1 = r2 = (const float4*)(mesh + (size_t)vcl * 64 + c0);
    }
    unsigned* dst = (unsigned*)(Adst + v * A_STRIDE + c0);
#pragma unroll
    for (int j = 0; j < 4; j++) {
        const float4 a0 = r0[j], a1 = r1[j], a2 = r2[j];
        uint4 u;
        u.x = f2tf32(fmaf(w0, a0.x, fmaf(w1, a1.x, w2 * a2.x)));
        u.y = f2tf32(fmaf(w0, a0.y, fmaf(w1, a1.y, w2 * a2.y)));
        u.z = f2tf32(fmaf(w0, a0.z, fmaf(w1, a1.z, w2 * a2.z)));
        u.w = f2tf32(fmaf(w0, a0.w, fmaf(w1, a1.w, w2 * a2.w)));
        *(uint4*)(dst + j * 4) = u;
    }
}

// ---------------------------------------------------------------------------
// Main kernel: 512 threads, 16 warps (2 M-rows x 8 N-cols), warp tile 64x32.
// ldmatrix.x4 A-fragments + paired LDS.128 B-fragments, double-buffered A/B.
// ---------------------------------------------------------------------------
__global__ __launch_bounds__(512, 1)
void conv_mma_kernel(const float* __restrict__ mesh,
                     const float* __restrict__ bary,
                     const float* __restrict__ bias,
                     float* __restrict__ out) {
    extern __shared__ __align__(128) char smem[];
    const uint32_t sbase = smem_u32(smem);

    const int tid  = threadIdx.x;
    const int lane = tid & 31;
    const int wid  = tid >> 5;
    const int wm   = wid >> 3;           // 0..1
    const int wn2  = wid & 7;            // 0..7  (32-col groups)
    const int w4   = wn2 >> 1;           // 64-col group index (matches g_W 'w')
    const int thal = (wn2 & 1) * 4;      // tt offset within the 64-col group
    const int ppair = thal >> 1;         // 0 or 2 : first pair index
    const int nt   = blockIdx.x;         // 0..1
    const int vt   = blockIdx.y;         // 0..390

    if (tid < 64) ((float*)(smem + SM_BIAS))[tid] = bias[tid];

    const char* gW = (const char*)g_W + (size_t)nt * 41 * 65536;
    const int v   = tid >> 2;            // 0..127 (local vertex)
    const int c0  = (tid & 3) * 16;      // channel quarter
    const int vg  = vt * BM + v;
    const int vcl = vg < NV ? vg : NV - 1;
    const float* bary_v = bary + (size_t)vcl * 240;   // 40*3*2

    // ldmatrix per-lane address pieces: row = lane&15 (matrices 0/1),
    // colhalf = lane>>4 (matrices 2/3 take cols 4..7)
    const int lrow = lane & 15;
    const int lch  = lane >> 4;
    const uint32_t aoff = (uint32_t)(((wm * 64 + lrow) * A_STRIDE + lch * 4) * 4);

    float acc[4][4][4];
#pragma unroll
    for (int mt = 0; mt < 4; mt++)
#pragma unroll
        for (int t = 0; t < 4; t++)
#pragma unroll
            for (int q = 0; q < 4; q++) acc[mt][t][q] = 0.f;

    // ---------------- prologue: stage 0 ----------------
    {
        const uint32_t bdst = sbase + SM_B0 + tid * 16;
        const char*    bsrc = gW + tid * 16;
#pragma unroll
        for (int i = 0; i < 8; i++) cp16(bdst + i * 8192, bsrc + i * 8192);
        cp_commit();
        const float2 p0 = *(const float2*)(bary_v + 0);
        const float2 p1 = *(const float2*)(bary_v + 2);
        const float2 p2 = *(const float2*)(bary_v + 4);
        build_a((float*)(smem + SM_A0), mesh, 0, v, c0, vcl, p0, p1, p2);
        cp_wait0();
        __syncthreads();
    }

    // ---------------- main loop ----------------
    for (int c = 0; c < CHUNKS; c++) {
        const int s   = c & 1;
        const int ncn = c + 1;
        float2 p0 = make_float2(0.f, 0.f), p1 = p0, p2 = p0;

        if (ncn < CHUNKS) {
            // issue B load for next chunk into buffer s^1
            const uint32_t bdst = sbase + (s ? SM_B0 : SM_B1) + tid * 16;
            const char*    bsrc = gW + (size_t)ncn * 65536 + tid * 16;
#pragma unroll
            for (int i = 0; i < 8; i++) cp16(bdst + i * 8192, bsrc + i * 8192);
            cp_commit();
            if (ncn < 40) {   // prefetch bary (DRAM latency hidden by mma)
                p0 = *(const float2*)(bary_v + ncn * 6 + 0);
                p1 = *(const float2*)(bary_v + ncn * 6 + 2);
                p2 = *(const float2*)(bary_v + ncn * 6 + 4);
            }
        }

        // ---- mma over buffers s ----
        const uint32_t Aaddr = sbase + (s ? SM_A1 : SM_A0) + aoff;
        const float*   Bb    = (const float*)(smem + (s ? SM_B1 : SM_B0));
#pragma unroll
        for (int ks = 0; ks < 8; ks++) {
            unsigned af[4][4];
#pragma unroll
            for (int mt = 0; mt < 4; mt++)
                ldmA(af[mt], Aaddr + (uint32_t)((mt * 16 * A_STRIDE + ks * 8) * 4));

            unsigned bf[4][2];
            {
                const float4 bv0 = *(const float4*)(Bb +
                    ((((w4 * 4 + ppair + 0) * 8) + ks) * 32 + lane) * 4);
                const float4 bv1 = *(const float4*)(Bb +
                    ((((w4 * 4 + ppair + 1) * 8) + ks) * 32 + lane) * 4);
                bf[0][0] = __float_as_uint(bv0.x); bf[0][1] = __float_as_uint(bv0.y);
                bf[1][0] = __float_as_uint(bv0.z); bf[1][1] = __float_as_uint(bv0.w);
                bf[2][0] = __float_as_uint(bv1.x); bf[2][1] = __float_as_uint(bv1.y);
                bf[3][0] = __float_as_uint(bv1.z); bf[3][1] = __float_as_uint(bv1.w);
            }
#pragma unroll
            for (int mt = 0; mt < 4; mt++)
#pragma unroll
                for (int t = 0; t < 4; t++)
                    mma8(acc[mt][t], af[mt], bf[t]);
        }

        // ---- build next A into buffer s^1 ----
        if (ncn < CHUNKS)
            build_a((float*)(smem + (s ? SM_A0 : SM_A1)), mesh, ncn, v, c0, vcl,
                    p0, p1, p2);

        cp_wait0();
        __syncthreads();
    }

    // ---------------- epilogue: +bias, relu, store ----------------
    const float* sbias = (const float*)(smem + SM_BIAS);
#pragma unroll
    for (int mt = 0; mt < 4; mt++) {
        const int row0 = vt * BM + wm * 64 + mt * 16 + (lane >> 2);
        const int row1 = row0 + 8;
#pragma unroll
        for (int t = 0; t < 4; t++) {
            const int cloc = (thal + t) * 8 + (lane & 3) * 2;  // 0..63 within group
            const int col  = nt * 256 + w4 * 64 + cloc;
            const float b0 = sbias[cloc];
            const float b1 = sbias[cloc + 1];
            if (row0 < NV) {
                float2 o0;
                o0.x = fmaxf(acc[mt][t][0] + b0, 0.f);
                o0.y = fmaxf(acc[mt][t][1] + b1, 0.f);
                *(float2*)(out + (size_t)row0 * 512 + col) = o0;
            }
            if (row1 < NV) {
                float2 o1;
                o1.x = fmaxf(acc[mt][t][2] + b0, 0.f);
                o1.y = fmaxf(acc[mt][t][3] + b1, 0.f);
                *(float2*)(out + (size_t)row1 * 512 + col) = o1;
            }
        }
    }
}

extern "C" void kernel_launch(void* const* d_in, const int* in_sizes, int n_in,
                              void* d_out, int out_size) {
    const float* mesh  = (const float*)d_in[0];  // (50000, 64)
    const float* bary  = (const float*)d_in[1];  // (50000, 5, 8, 3, 2)
    const float* nw    = (const float*)d_in[2];  // (64, 5, 8, 64)
    const float* cw    = (const float*)d_in[3];  // (64, 1, 64)
    const float* bias  = (const float*)d_in[4];  // (64,)
    const float* coeff = (const float*)d_in[5];  // (5, 8, 40)
    float* out = (float*)d_out;                  // (50000, 8, 64)

    static int smem_set = 0;
    if (!smem_set) {
        cudaFuncSetAttribute(conv_mma_kernel,
                             cudaFuncAttributeMaxDynamicSharedMemorySize, SMEM_TOTAL);
        smem_set = 1;
    }

    fold_kernel<<<dim3(41, 64), 64>>>(nw, cw, coeff);
    conv_mma_kernel<<<dim3(2, NVT), 512, SMEM_TOTAL>>>(mesh, bary, bias, out);
}

// round 13
// speedup vs baseline: 6.5680x; 1.4328x over previous
#include <cuda_runtime.h>
#include <cuda_fp16.h>
#include <cstdint>

#define NV      50000
#define BM      128
#define NVT     ((NV + BM - 1) / BM)   // 391
#define CHUNKS  41
#define A_STRIDE_H 72                  // halves per vertex row (pad vs 64)

// SMEM byte offsets
#define SM_A0    0
#define SM_A1    18432                 // 128*72*2
#define SM_B0    36864
#define SM_B1    69632                 // +32KB
#define SM_BIAS  102400
#define SMEM_TOTAL 102656

// Folded weights, fp16, fragment-major, chunk-blocked, B-paired:
// [nt(2)][chunk(41)][w4(4)][pair(4)][ks(4)][lane(32)][inp(2)][reg(2)][half(2)]
// -> 2.625 MB (L2-resident)
__device__ __align__(256) __half g_W[2u * 41 * 16384];

// ---------------------------------------------------------------------------
// helpers
// ---------------------------------------------------------------------------
__device__ __forceinline__ uint32_t smem_u32(const void* p) {
    uint32_t a;
    asm("{ .reg .u64 t; cvta.to.shared.u64 t, %1; cvt.u32.u64 %0, t; }"
        : "=r"(a) : "l"(p));
    return a;
}
__device__ __forceinline__ void cp16(uint32_t d, const void* s) {
    asm volatile("cp.async.cg.shared.global [%0], [%1], 16;"
                 :: "r"(d), "l"(s) : "memory");
}
__device__ __forceinline__ void cp_commit() {
    asm volatile("cp.async.commit_group;" ::: "memory");
}
__device__ __forceinline__ void cp_wait0() {
    asm volatile("cp.async.wait_group 0;" ::: "memory");
}
__device__ __forceinline__ void ldmA(unsigned* r, uint32_t addr) {
    asm volatile("ldmatrix.sync.aligned.m8n8.x4.shared.b16 {%0,%1,%2,%3}, [%4];"
                 : "=r"(r[0]), "=r"(r[1]), "=r"(r[2]), "=r"(r[3]) : "r"(addr));
}
__device__ __forceinline__ void mma16(float* d, const unsigned* a, const unsigned* b) {
    asm volatile(
        "mma.sync.aligned.m16n8k16.row.col.f32.f16.f16.f32 "
        "{%0,%1,%2,%3}, {%4,%5,%6,%7}, {%8,%9}, {%0,%1,%2,%3};"
        : "+f"(d[0]), "+f"(d[1]), "+f"(d[2]), "+f"(d[3])
        : "r"(a[0]), "r"(a[1]), "r"(a[2]), "r"(a[3]), "r"(b[0]), "r"(b[1]));
}

// ---------------------------------------------------------------------------
// Fold kernel: W'[k=(m,c)][n=(o,t)] = sum_{r2,a2} coeff[r2,a2,m] * nw[t,r2,(a2+o)&7,c]
// (m=40 -> center row = cw[t][c], replicated over o). Written fp16,
// fragment-major per the g_W layout above (m16n8k16 B-fragments, paired).
// ---------------------------------------------------------------------------
__global__ void fold_kernel(const float* __restrict__ nw,
                            const float* __restrict__ cw,
                            const float* __restrict__ coeff) {
    const int m = blockIdx.x;    // 0..40
    const int t = blockIdx.y;    // 0..63
    const int c = threadIdx.x;   // 0..63

    float vals[8];
    if (m < 40) {
        float nwreg[40], coreg[40];
#pragma unroll
        for (int ra = 0; ra < 40; ra++)
            nwreg[ra] = nw[(t * 40 + ra) * 64 + c];
#pragma unroll
        for (int ra = 0; ra < 40; ra++)
            coreg[ra] = coeff[ra * 40 + m];
#pragma unroll
        for (int o = 0; o < 8; o++) {
            float acc = 0.f;
#pragma unroll
            for (int r = 0; r < 5; r++)
#pragma unroll
                for (int a = 0; a < 8; a++)
                    acc = fmaf(coreg[r * 8 + a], nwreg[r * 8 + ((a + o) & 7)], acc);
            vals[o] = acc;
        }
    } else {
        const float vv = cw[t * 64 + c];
#pragma unroll
        for (int o = 0; o < 8; o++) vals[o] = vv;
    }

    // m16n8k16 B-fragment coords for k index c (0..63):
    const int ks   = c >> 4;          // k16 step
    const int kk   = c & 15;          // k within step
    const int reg  = kk >> 3;         // b0: k0-7, b1: k8-15
    const int half = kk & 1;
    const int tin  = (kk & 7) >> 1;   // tid_in_group
#pragma unroll
    for (int o = 0; o < 8; o++) {
        const int n    = o * 64 + t;
        const int nt   = n >> 8;
        const int nn   = n & 255;
        const int w4   = nn >> 6;
        const int tt   = (nn >> 3) & 7;
        const int pair = tt >> 1, inp = tt & 1;
        const int lane = (n & 7) * 4 + tin;
        const size_t idx =
            ((((((size_t)(nt * 41 + m) * 4 + w4) * 4 + pair) * 4 + ks) * 32 + lane) * 8)
            + inp * 4 + reg * 2 + half;
        g_W[idx] = __float2half_rn(vals[o]);
    }
}

// ---------------------------------------------------------------------------
// A-tile builder: barycentric gather + interp + fp16 cvt into As[v][c] (pad 72 h).
// 4 threads per vertex, each handles 16 contiguous channels.
// ---------------------------------------------------------------------------
__device__ __forceinline__ void build_a(char* abase, const float* __restrict__ mesh,
                                        int chunk, int v, int c0, int vcl,
                                        float2 p0, float2 p1, float2 p2) {
    float w0, w1, w2;
    const float4 *r0, *r1, *r2;
    if (chunk < 40) {
        w0 = p0.y; w1 = p1.y; w2 = p2.y;
        r0 = (const float4*)(mesh + (size_t)(int)p0.x * 64 + c0);
        r1 = (const float4*)(mesh + (size_t)(int)p1.x * 64 + c0);
        r2 = (const float4*)(mesh + (size_t)(int)p2.x * 64 + c0);
    } else {  // center: raw mesh row
        w0 = 1.f; w1 = 0.f; w2 = 0.f;
        r0 = r1 = r2 = (const float4*)(mesh + (size_t)vcl * 64 + c0);
    }
    char* dst = abase + (v * A_STRIDE_H + c0) * 2;
#pragma unroll
    for (int j = 0; j < 4; j++) {
        const float4 a0 = r0[j], a1 = r1[j], a2 = r2[j];
        const float vx = fmaf(w0, a0.x, fmaf(w1, a1.x, w2 * a2.x));
        const float vy = fmaf(w0, a0.y, fmaf(w1, a1.y, w2 * a2.y));
        const float vz = fmaf(w0, a0.z, fmaf(w1, a1.z, w2 * a2.z));
        const float vw = fmaf(w0, a0.w, fmaf(w1, a1.w, w2 * a2.w));
        const __half2 h0 = __floats2half2_rn(vx, vy);
        const __half2 h1 = __floats2half2_rn(vz, vw);
        uint2 u;
        u.x = *(const unsigned*)&h0;
        u.y = *(const unsigned*)&h1;
        *(uint2*)(dst + j * 8) = u;
    }
}

// ---------------------------------------------------------------------------
// Main kernel: 512 threads, 16 warps (2 M-rows x 8 N-cols), warp tile 64x32.
// fp16 m16n8k16, ldmatrix.x4 A + paired LDS.128 B, double-buffered A/B.
// ---------------------------------------------------------------------------
__global__ __launch_bounds__(512, 1)
void conv_mma_kernel(const float* __restrict__ mesh,
                     const float* __restrict__ bary,
                     const float* __restrict__ bias,
                     float* __restrict__ out) {
    extern __shared__ __align__(128) char smem[];
    const uint32_t sbase = smem_u32(smem);

    const int tid  = threadIdx.x;
    const int lane = tid & 31;
    const int wid  = tid >> 5;
    const int wm   = wid >> 3;           // 0..1
    const int wn2  = wid & 7;            // 0..7  (32-col groups)
    const int w4   = wn2 >> 1;           // 64-col group index (matches g_W 'w4')
    const int thal = (wn2 & 1) * 4;      // tt offset within the 64-col group
    const int ppair = thal >> 1;         // 0 or 2 : first pair index
    const int nt   = blockIdx.x;         // 0..1
    const int vt   = blockIdx.y;         // 0..390

    if (tid < 64) ((float*)(smem + SM_BIAS))[tid] = bias[tid];

    const char* gW = (const char*)g_W + (size_t)nt * 41 * 32768;
    const int v   = tid >> 2;            // 0..127 (local vertex)
    const int c0  = (tid & 3) * 16;      // channel quarter
    const int vg  = vt * BM + v;
    const int vcl = vg < NV ? vg : NV - 1;
    const float* bary_v = bary + (size_t)vcl * 240;   // 40*3*2

    // ldmatrix per-lane address: lanes 0-7 m0 (rows 0-7, k0-7), 8-15 m1 (rows
    // 8-15), 16-23 m2 (rows 0-7, k8-15: +16B), 24-31 m3.
    const int lrow = lane & 15;
    const int lch  = lane >> 4;
    const uint32_t aoff = (uint32_t)((wm * 64 + lrow) * (A_STRIDE_H * 2) + lch * 16);

    float acc[4][4][4];
#pragma unroll
    for (int mt = 0; mt < 4; mt++)
#pragma unroll
        for (int t = 0; t < 4; t++)
#pragma unroll
            for (int q = 0; q < 4; q++) acc[mt][t][q] = 0.f;

    // ---------------- prologue: stage 0 ----------------
    {
        const uint32_t bdst = sbase + SM_B0 + tid * 16;
        const char*    bsrc = gW + tid * 16;
#pragma unroll
        for (int i = 0; i < 4; i++) cp16(bdst + i * 8192, bsrc + i * 8192);
        cp_commit();
        const float2 p0 = *(const float2*)(bary_v + 0);
        const float2 p1 = *(const float2*)(bary_v + 2);
        const float2 p2 = *(const float2*)(bary_v + 4);
        build_a(smem + SM_A0, mesh, 0, v, c0, vcl, p0, p1, p2);
        cp_wait0();
        __syncthreads();
    }

    // ---------------- main loop ----------------
    for (int c = 0; c < CHUNKS; c++) {
        const int s   = c & 1;
        const int ncn = c + 1;
        float2 p0 = make_float2(0.f, 0.f), p1 = p0, p2 = p0;

        if (ncn < CHUNKS) {
            // issue B load for next chunk into buffer s^1
            const uint32_t bdst = sbase + (s ? SM_B0 : SM_B1) + tid * 16;
            const char*    bsrc = gW + (size_t)ncn * 32768 + tid * 16;
#pragma unroll
            for (int i = 0; i < 4; i++) cp16(bdst + i * 8192, bsrc + i * 8192);
            cp_commit();
            if (ncn < 40) {   // prefetch bary
                p0 = *(const float2*)(bary_v + ncn * 6 + 0);
                p1 = *(const float2*)(bary_v + ncn * 6 + 2);
                p2 = *(const float2*)(bary_v + ncn * 6 + 4);
            }
        }

        // ---- mma over buffers s ----
        const uint32_t Aaddr = sbase + (s ? SM_A1 : SM_A0) + aoff;
        const char*    Bb    = smem + (s ? SM_B1 : SM_B0) + w4 * 8192;
#pragma unroll
        for (int ks = 0; ks < 4; ks++) {
            unsigned af[4][4];
#pragma unroll
            for (int mt = 0; mt < 4; mt++)
                ldmA(af[mt], Aaddr + (uint32_t)(mt * 16 * A_STRIDE_H * 2 + ks * 32));

            unsigned bf[4][2];
            {
                const uint4 bv0 = *(const uint4*)(Bb +
                    (((ppair + 0) * 4 + ks) * 32 + lane) * 16);
                const uint4 bv1 = *(const uint4*)(Bb +
                    (((ppair + 1) * 4 + ks) * 32 + lane) * 16);
                bf[0][0] = bv0.x; bf[0][1] = bv0.y;
                bf[1][0] = bv0.z; bf[1][1] = bv0.w;
                bf[2][0] = bv1.x; bf[2][1] = bv1.y;
                bf[3][0] = bv1.z; bf[3][1] = bv1.w;
            }
#pragma unroll
            for (int mt = 0; mt < 4; mt++)
#pragma unroll
                for (int t = 0; t < 4; t++)
                    mma16(acc[mt][t], af[mt], bf[t]);
        }

        // ---- build next A into buffer s^1 ----
        if (ncn < CHUNKS)
            build_a(smem + (s ? SM_A0 : SM_A1), mesh, ncn, v, c0, vcl,
                    p0, p1, p2);

        cp_wait0();
        __syncthreads();
    }

    // ---------------- epilogue: +bias, relu, store ----------------
    const float* sbias = (const float*)(smem + SM_BIAS);
#pragma unroll
    for (int mt = 0; mt < 4; mt++) {
        const int row0 = vt * BM + wm * 64 + mt * 16 + (lane >> 2);
        const int row1 = row0 + 8;
#pragma unroll
        for (int t = 0; t < 4; t++) {
            const int cloc = (thal + t) * 8 + (lane & 3) * 2;  // 0..63 within group
            const int col  = nt * 256 + w4 * 64 + cloc;
            const float b0 = sbias[cloc];
            const float b1 = sbias[cloc + 1];
            if (row0 < NV) {
                float2 o0;
                o0.x = fmaxf(acc[mt][t][0] + b0, 0.f);
                o0.y = fmaxf(acc[mt][t][1] + b1, 0.f);
                *(float2*)(out + (size_t)row0 * 512 + col) = o0;
            }
            if (row1 < NV) {
                float2 o1;
                o1.x = fmaxf(acc[mt][t][2] + b0, 0.f);
                o1.y = fmaxf(acc[mt][t][3] + b1, 0.f);
                *(float2*)(out + (size_t)row1 * 512 + col) = o1;
            }
        }
    }
}

extern "C" void kernel_launch(void* const* d_in, const int* in_sizes, int n_in,
                              void* d_out, int out_size) {
    const float* mesh  = (const float*)d_in[0];  // (50000, 64)
    const float* bary  = (const float*)d_in[1];  // (50000, 5, 8, 3, 2)
    const float* nw    = (const float*)d_in[2];  // (64, 5, 8, 64)
    const float* cw    = (const float*)d_in[3];  // (64, 1, 64)
    const float* bias  = (const float*)d_in[4];  // (64,)
    const float* coeff = (const float*)d_in[5];  // (5, 8, 40)
    float* out = (float*)d_out;                  // (50000, 8, 64)

    static int smem_set = 0;
    if (!smem_set) {
        cudaFuncSetAttribute(conv_mma_kernel,
                             cudaFuncAttributeMaxDynamicSharedMemorySize, SMEM_TOTAL);
        smem_set = 1;
    }

    fold_kernel<<<dim3(41, 64), 64>>>(nw, cw, coeff);
    conv_mma_kernel<<<dim3(2, NVT), 512, SMEM_TOTAL>>>(mesh, bary, bias, out);
}

// round 14
// speedup vs baseline: 11.3016x; 1.7207x over previous
#include <cuda_runtime.h>
#include <cuda_fp16.h>
#include <cstdint>

#define NV      50000
#define BM      128
#define NVT     ((NV + BM - 1) / BM)   // 391
#define CHUNKS  41
#define A_STRIDE_H 72                  // halves per vertex row (pad vs 64)

// SMEM byte offsets
#define SM_A0    0
#define SM_A1    18432                 // 128*72*2
#define SM_BIAS  36864
#define SMEM_TOTAL 37120

// Folded weights, fp16, fragment-major, chunk-blocked, B-paired:
// [nt(2)][chunk(41)][w4(4)][pair(4)][ks(4)][lane(32)][inp(2)][reg(2)][half(2)]
// -> 2.625 MB (L2-resident; each thread's fragment pair = contiguous 16B)
__device__ __align__(256) __half g_W[2u * 41 * 16384];

// Mesh signal pre-converted to fp16: 50000 x 64 = 6.4 MB
__device__ __align__(256) __half g_mesh[NV * 64];

// ---------------------------------------------------------------------------
// helpers
// ---------------------------------------------------------------------------
__device__ __forceinline__ uint32_t smem_u32(const void* p) {
    uint32_t a;
    asm("{ .reg .u64 t; cvta.to.shared.u64 t, %1; cvt.u32.u64 %0, t; }"
        : "=r"(a) : "l"(p));
    return a;
}
__device__ __forceinline__ void ldmA(unsigned* r, uint32_t addr) {
    asm volatile("ldmatrix.sync.aligned.m8n8.x4.shared.b16 {%0,%1,%2,%3}, [%4];"
                 : "=r"(r[0]), "=r"(r[1]), "=r"(r[2]), "=r"(r[3]) : "r"(addr));
}
__device__ __forceinline__ void mma16(float* d, const unsigned* a, const unsigned* b) {
    asm volatile(
        "mma.sync.aligned.m16n8k16.row.col.f32.f16.f16.f32 "
        "{%0,%1,%2,%3}, {%4,%5,%6,%7}, {%8,%9}, {%0,%1,%2,%3};"
        : "+f"(d[0]), "+f"(d[1]), "+f"(d[2]), "+f"(d[3])
        : "r"(a[0]), "r"(a[1]), "r"(a[2]), "r"(a[3]), "r"(b[0]), "r"(b[1]));
}

// ---------------------------------------------------------------------------
// Mesh fp16 conversion: g_mesh[i] = half(mesh[i])
// ---------------------------------------------------------------------------
__global__ void mesh_half_kernel(const float* __restrict__ mesh) {
    const int i = (blockIdx.x * blockDim.x + threadIdx.x) * 4;
    if (i < NV * 64) {
        const float4 v = *(const float4*)(mesh + i);
        const __half2 h0 = __floats2half2_rn(v.x, v.y);
        const __half2 h1 = __floats2half2_rn(v.z, v.w);
        uint2 u;
        u.x = *(const unsigned*)&h0;
        u.y = *(const unsigned*)&h1;
        *(uint2*)(&g_mesh[i]) = u;
    }
}

// ---------------------------------------------------------------------------
// Fold kernel: W'[k=(m,c)][n=(o,t)] = sum_{r2,a2} coeff[r2,a2,m] * nw[t,r2,(a2+o)&7,c]
// (m=40 -> center row = cw[t][c], replicated over o). Written fp16,
// fragment-major per the g_W layout above (m16n8k16 B-fragments, paired).
// ---------------------------------------------------------------------------
__global__ void fold_kernel(const float* __restrict__ nw,
                            const float* __restrict__ cw,
                            const float* __restrict__ coeff) {
    const int m = blockIdx.x;    // 0..40
    const int t = blockIdx.y;    // 0..63
    const int c = threadIdx.x;   // 0..63

    float vals[8];
    if (m < 40) {
        float nwreg[40], coreg[40];
#pragma unroll
        for (int ra = 0; ra < 40; ra++)
            nwreg[ra] = nw[(t * 40 + ra) * 64 + c];
#pragma unroll
        for (int ra = 0; ra < 40; ra++)
            coreg[ra] = coeff[ra * 40 + m];
#pragma unroll
        for (int o = 0; o < 8; o++) {
            float acc = 0.f;
#pragma unroll
            for (int r = 0; r < 5; r++)
#pragma unroll
                for (int a = 0; a < 8; a++)
                    acc = fmaf(coreg[r * 8 + a], nwreg[r * 8 + ((a + o) & 7)], acc);
            vals[o] = acc;
        }
    } else {
        const float vv = cw[t * 64 + c];
#pragma unroll
        for (int o = 0; o < 8; o++) vals[o] = vv;
    }

    // m16n8k16 B-fragment coords for k index c (0..63):
    const int ks   = c >> 4;          // k16 step
    const int kk   = c & 15;          // k within step
    const int reg  = kk >> 3;         // b0: k0-7, b1: k8-15
    const int half = kk & 1;
    const int tin  = (kk & 7) >> 1;   // tid_in_group
#pragma unroll
    for (int o = 0; o < 8; o++) {
        const int n    = o * 64 + t;
        const int nt   = n >> 8;
        const int nn   = n & 255;
        const int w4   = nn >> 6;
        const int tt   = (nn >> 3) & 7;
        const int pair = tt >> 1, inp = tt & 1;
        const int lane = (n & 7) * 4 + tin;
        const size_t idx =
            ((((((size_t)(nt * 41 + m) * 4 + w4) * 4 + pair) * 4 + ks) * 32 + lane) * 8)
            + inp * 4 + reg * 2 + half;
        g_W[idx] = __float2half_rn(vals[o]);
    }
}

// ---------------------------------------------------------------------------
// A-tile builder: fp16 mesh gather + fp32 interp + fp16 store into As[v][c].
// 4 threads per vertex, each handles 16 contiguous channels (2x LDG.128/row).
// ---------------------------------------------------------------------------
__device__ __forceinline__ void build_a(char* abase, int chunk, int v, int c0,
                                        int vcl, float2 p0, float2 p1, float2 p2) {
    float w0, w1, w2;
    const uint4 *r0, *r1, *r2;
    if (chunk < 40) {
        w0 = p0.y; w1 = p1.y; w2 = p2.y;
        r0 = (const uint4*)(g_mesh + (size_t)(int)p0.x * 64 + c0);
        r1 = (const uint4*)(g_mesh + (size_t)(int)p1.x * 64 + c0);
        r2 = (const uint4*)(g_mesh + (size_t)(int)p2.x * 64 + c0);
    } else {  // center: raw mesh row
        w0 = 1.f; w1 = 0.f; w2 = 0.f;
        r0 = r1 = r2 = (const uint4*)(g_mesh + (size_t)vcl * 64 + c0);
    }
    char* dst = abase + (v * A_STRIDE_H + c0) * 2;
#pragma unroll
    for (int j = 0; j < 2; j++) {          // 2 x 8 halves per row
        const uint4 a0 = r0[j], a1 = r1[j], a2 = r2[j];
        const unsigned* u0 = (const unsigned*)&a0;
        const unsigned* u1 = (const unsigned*)&a1;
        const unsigned* u2 = (const unsigned*)&a2;
        unsigned res[4];
#pragma unroll
        for (int q = 0; q < 4; q++) {
            const float2 f0 = __half22float2(*(const __half2*)&u0[q]);
            const float2 f1 = __half22float2(*(const __half2*)&u1[q]);
            const float2 f2 = __half22float2(*(const __half2*)&u2[q]);
            const float rx = fmaf(w0, f0.x, fmaf(w1, f1.x, w2 * f2.x));
            const float ry = fmaf(w0, f0.y, fmaf(w1, f1.y, w2 * f2.y));
            const __half2 h = __floats2half2_rn(rx, ry);
            res[q] = *(const unsigned*)&h;
        }
        *(uint4*)(dst + j * 16) = make_uint4(res[0], res[1], res[2], res[3]);
    }
}

// ---------------------------------------------------------------------------
// Main kernel: 512 threads, 16 warps (2 M-rows x 8 N-cols), warp tile 64x32.
// fp16 m16n8k16, ldmatrix.x4 A; B fragments stream straight from L2 via
// LDG.128 with 1-step register pipelining (no SMEM staging for B).
// ---------------------------------------------------------------------------
__global__ __launch_bounds__(512, 1)
void conv_mma_kernel(const float* __restrict__ bary,
                     const float* __restrict__ bias,
                     float* __restrict__ out) {
    extern __shared__ __align__(128) char smem[];
    const uint32_t sbase = smem_u32(smem);

    const int tid  = threadIdx.x;
    const int lane = tid & 31;
    const int wid  = tid >> 5;
    const int wm   = wid >> 3;           // 0..1
    const int wn2  = wid & 7;            // 0..7  (32-col groups)
    const int w4   = wn2 >> 1;           // 64-col group index (matches g_W 'w4')
    const int thal = (wn2 & 1) * 4;      // tt offset within the 64-col group
    const int ppair = thal >> 1;         // 0 or 2 : first pair index
    const int nt   = blockIdx.x;         // 0..1
    const int vt   = blockIdx.y;         // 0..390

    if (tid < 64) ((float*)(smem + SM_BIAS))[tid] = bias[tid];

    // Per-warp B base in gmem (fragment-major; lane offset folded in)
    const char* gWb = (const char*)g_W + (size_t)nt * 41 * 32768
                      + w4 * 8192 + lane * 16;

    const int v   = tid >> 2;            // 0..127 (local vertex)
    const int c0  = (tid & 3) * 16;      // channel quarter
    const int vg  = vt * BM + v;
    const int vcl = vg < NV ? vg : NV - 1;
    const float* bary_v = bary + (size_t)vcl * 240;   // 40*3*2

    // ldmatrix per-lane address: lanes 0-7 m0 (rows 0-7, k0-7), 8-15 m1 (rows
    // 8-15), 16-23 m2 (rows 0-7, k8-15: +16B), 24-31 m3.
    const int lrow = lane & 15;
    const int lch  = lane >> 4;
    const uint32_t aoff = (uint32_t)((wm * 64 + lrow) * (A_STRIDE_H * 2) + lch * 16);

    float acc[4][4][4];
#pragma unroll
    for (int mt = 0; mt < 4; mt++)
#pragma unroll
        for (int t = 0; t < 4; t++)
#pragma unroll
            for (int q = 0; q < 4; q++) acc[mt][t][q] = 0.f;

    // ---------------- prologue: stage 0 ----------------
    uint4 bc0, bc1;   // current-ks B fragments (pair 0, pair 1)
    {
        bc0 = *(const uint4*)(gWb + ((ppair + 0) * 4 + 0) * 512);
        bc1 = *(const uint4*)(gWb + ((ppair + 1) * 4 + 0) * 512);
        const float2 p0 = *(const float2*)(bary_v + 0);
        const float2 p1 = *(const float2*)(bary_v + 2);
        const float2 p2 = *(const float2*)(bary_v + 4);
        build_a(smem + SM_A0, 0, v, c0, vcl, p0, p1, p2);
        __syncthreads();
    }

    // ---------------- main loop ----------------
    for (int c = 0; c < CHUNKS; c++) {
        const int s   = c & 1;
        const int ncn = c + 1;
        float2 p0 = make_float2(0.f, 0.f), p1 = p0, p2 = p0;

        if (ncn < 40) {   // prefetch bary for next chunk
            p0 = *(const float2*)(bary_v + ncn * 6 + 0);
            p1 = *(const float2*)(bary_v + ncn * 6 + 2);
            p2 = *(const float2*)(bary_v + ncn * 6 + 4);
        }

        // ---- mma over A buffer s; B streams from L2 one ks ahead ----
        const uint32_t Aaddr = sbase + (s ? SM_A1 : SM_A0) + aoff;
#pragma unroll
        for (int ks = 0; ks < 4; ks++) {
            // issue next-step B loads (ks+1, or next chunk's ks=0)
            const int nc = (ks < 3) ? c : (c < 40 ? c + 1 : c);
            const int nk = (ks + 1) & 3;
            const char* nb = gWb + (size_t)nc * 32768;
            const uint4 bn0 = *(const uint4*)(nb + ((ppair + 0) * 4 + nk) * 512);
            const uint4 bn1 = *(const uint4*)(nb + ((ppair + 1) * 4 + nk) * 512);

            unsigned af[4][4];
#pragma unroll
            for (int mt = 0; mt < 4; mt++)
                ldmA(af[mt], Aaddr + (uint32_t)(mt * 16 * A_STRIDE_H * 2 + ks * 32));

            unsigned bf[4][2];
            bf[0][0] = bc0.x; bf[0][1] = bc0.y;
            bf[1][0] = bc0.z; bf[1][1] = bc0.w;
            bf[2][0] = bc1.x; bf[2][1] = bc1.y;
            bf[3][0] = bc1.z; bf[3][1] = bc1.w;
#pragma unroll
            for (int mt = 0; mt < 4; mt++)
#pragma unroll
                for (int t = 0; t < 4; t++)
                    mma16(acc[mt][t], af[mt], bf[t]);

            bc0 = bn0; bc1 = bn1;
        }

        // ---- build next A into buffer s^1 ----
        if (ncn < CHUNKS)
            build_a(smem + (s ? SM_A0 : SM_A1), ncn, v, c0, vcl, p0, p1, p2);

        __syncthreads();
    }

    // ---------------- epilogue: +bias, relu, store ----------------
    const float* sbias = (const float*)(smem + SM_BIAS);
#pragma unroll
    for (int mt = 0; mt < 4; mt++) {
        const int row0 = vt * BM + wm * 64 + mt * 16 + (lane >> 2);
        const int row1 = row0 + 8;
#pragma unroll
        for (int t = 0; t < 4; t++) {
            const int cloc = (thal + t) * 8 + (lane & 3) * 2;  // 0..63 within group
            const int col  = nt * 256 + w4 * 64 + cloc;
            const float b0 = sbias[cloc];
            const float b1 = sbias[cloc + 1];
            if (row0 < NV) {
                float2 o0;
                o0.x = fmaxf(acc[mt][t][0] + b0, 0.f);
                o0.y = fmaxf(acc[mt][t][1] + b1, 0.f);
                *(float2*)(out + (size_t)row0 * 512 + col) = o0;
            }
            if (row1 < NV) {
                float2 o1;
                o1.x = fmaxf(acc[mt][t][2] + b0, 0.f);
                o1.y = fmaxf(acc[mt][t][3] + b1, 0.f);
                *(float2*)(out + (size_t)row1 * 512 + col) = o1;
            }
        }
    }
}

extern "C" void kernel_launch(void* const* d_in, const int* in_sizes, int n_in,
                              void* d_out, int out_size) {
    const float* mesh  = (const float*)d_in[0];  // (50000, 64)
    const float* bary  = (const float*)d_in[1];  // (50000, 5, 8, 3, 2)
    const float* nw    = (const float*)d_in[2];  // (64, 5, 8, 64)
    const float* cw    = (const float*)d_in[3];  // (64, 1, 64)
    const float* bias  = (const float*)d_in[4];  // (64,)
    const float* coeff = (const float*)d_in[5];  // (5, 8, 40)
    float* out = (float*)d_out;                  // (50000, 8, 64)

    static int smem_set = 0;
    if (!smem_set) {
        cudaFuncSetAttribute(conv_mma_kernel,
                             cudaFuncAttributeMaxDynamicSharedMemorySize, SMEM_TOTAL);
        smem_set = 1;
    }

    mesh_half_kernel<<<(NV * 64 / 4 + 255) / 256, 256>>>(mesh);
    fold_kernel<<<dim3(41, 64), 64>>>(nw, cw, coeff);
    conv_mma_kernel<<<dim3(2, NVT), 512, SMEM_TOTAL>>>(bary, bias, out);
}